// round 2
// baseline (speedup 1.0000x reference)
#include <cuda_runtime.h>
#include <cstdint>

#define N_TOK   819200
#define BATCH   4096
#define HID     256
#define BN_EPS  1e-5f

// ---------------- device scratch (no allocations allowed) ----------------
__device__ __align__(16) float g_segsum[BATCH * HID];   // 4 MB
__device__ __align__(16) float g_h[BATCH * HID];        // 4 MB
__device__ __align__(16) float g_counts[BATCH];
__device__ __align__(16) float g_sums[HID];
__device__ __align__(16) float g_sumsq[HID];
__device__ float g_loss;
__device__ int   g_stride;   // 1 = int32 ids, 2 = int64 ids (read low word)

// ---------------- dtype detection: int64 vs int32 ids ----------------
// If ids are int64 (values < 2^31), every odd int32 word of the buffer is 0.
__global__ void k_detect(const int* __restrict__ tok) {
    __shared__ int any_nonzero;
    if (threadIdx.x == 0) any_nonzero = 0;
    __syncthreads();
    int v = tok[2 * threadIdx.x + 1];   // 64 threads -> inspects first 128 words
    if (v != 0) atomicOr(&any_nonzero, 1);
    __syncthreads();
    if (threadIdx.x == 0) g_stride = any_nonzero ? 1 : 2;
}

// ---------------- zero the accumulators ----------------
__global__ void k_init() {
    int i = blockIdx.x * blockDim.x + threadIdx.x;
    int nthreads = gridDim.x * blockDim.x;
    float4 z = make_float4(0.f, 0.f, 0.f, 0.f);
    float4* ss = (float4*)g_segsum;
    int n4 = (BATCH * HID) / 4;
    for (int idx = i; idx < n4; idx += nthreads) ss[idx] = z;
    if (i < BATCH) g_counts[i] = 0.f;
    if (i < HID) { g_sums[i] = 0.f; g_sumsq[i] = 0.f; }
    if (i == 0) g_loss = 0.f;
}

// ---------------- gather + segment sum ----------------
// One warp owns 64 contiguous tokens; lane l owns hidden dims [8l, 8l+8).
// Segment ids are sorted -> accumulate runs in registers, flush at boundaries
// with red.global.add.v4.f32 (2 instructions / lane / flush).
#define TOK_PER_WARP 64
#define GATHER_WARPS 8

__device__ __forceinline__ void flush_run(int seg, float4 a0, float4 a1,
                                          int runlen, int lane) {
    float* dst = g_segsum + (size_t)seg * HID + lane * 8;
    asm volatile("red.global.add.v4.f32 [%0], {%1,%2,%3,%4};"
                 :: "l"(dst), "f"(a0.x), "f"(a0.y), "f"(a0.z), "f"(a0.w)
                 : "memory");
    asm volatile("red.global.add.v4.f32 [%0], {%1,%2,%3,%4};"
                 :: "l"(dst + 4), "f"(a1.x), "f"(a1.y), "f"(a1.z), "f"(a1.w)
                 : "memory");
    if (lane == 0) atomicAdd(&g_counts[seg], (float)runlen);
}

__global__ void __launch_bounds__(GATHER_WARPS * 32)
k_gather(const int* __restrict__ tok, const int* __restrict__ seg,
         const float* __restrict__ emb) {
    const int stride = g_stride;
    const int lane = threadIdx.x & 31;
    const int warp_id = blockIdx.x * GATHER_WARPS + (threadIdx.x >> 5);
    const int t0 = warp_id * TOK_PER_WARP;

    const float4* __restrict__ embv = (const float4*)emb;

    float4 a0 = make_float4(0.f, 0.f, 0.f, 0.f);
    float4 a1 = make_float4(0.f, 0.f, 0.f, 0.f);
    int cur = seg[(size_t)t0 * stride];
    int runlen = 0;

    #pragma unroll 4
    for (int t = t0; t < t0 + TOK_PER_WARP; ++t) {
        int s = seg[(size_t)t * stride];
        if (s != cur) {
            flush_run(cur, a0, a1, runlen, lane);
            a0 = make_float4(0.f, 0.f, 0.f, 0.f);
            a1 = make_float4(0.f, 0.f, 0.f, 0.f);
            runlen = 0;
            cur = s;
        }
        int id = tok[(size_t)t * stride];
        const float4* row = embv + (size_t)id * (HID / 4) + lane * 2;
        float4 v0 = row[0];
        float4 v1 = row[1];
        a0.x += v0.x; a0.y += v0.y; a0.z += v0.z; a0.w += v0.w;
        a1.x += v1.x; a1.y += v1.y; a1.z += v1.z; a1.w += v1.w;
        ++runlen;
    }
    flush_run(cur, a0, a1, runlen, lane);
}

// ---------------- GEMM: h = (segsum * invc) @ W1^T + b1 ----------------
// NT layout (both K-major). 64x64 tile, BK=16, 256 threads, 4x4 microtile.
__global__ void __launch_bounds__(256)
k_gemm(const float* __restrict__ W1, const float* __restrict__ b1) {
    __shared__ float As[16][68];   // [k][m], padded
    __shared__ float Bs[16][68];   // [k][n], padded

    const int tid = threadIdx.x;
    const int m0 = blockIdx.y * 64;
    const int n0 = blockIdx.x * 64;
    const int tx = tid & 15;        // n subtile
    const int ty = tid >> 4;        // m subtile
    const int lrow = tid >> 2;      // 0..63 : row within tile for loads
    const int lk   = (tid & 3) * 4; // k quarter for loads

    float acc[4][4];
    #pragma unroll
    for (int i = 0; i < 4; i++)
        #pragma unroll
        for (int j = 0; j < 4; j++) acc[i][j] = 0.f;

    for (int k0 = 0; k0 < HID; k0 += 16) {
        float4 av = *(const float4*)&g_segsum[(size_t)(m0 + lrow) * HID + k0 + lk];
        float4 bv = *(const float4*)&W1[(size_t)(n0 + lrow) * HID + k0 + lk];
        __syncthreads();
        As[lk + 0][lrow] = av.x; As[lk + 1][lrow] = av.y;
        As[lk + 2][lrow] = av.z; As[lk + 3][lrow] = av.w;
        Bs[lk + 0][lrow] = bv.x; Bs[lk + 1][lrow] = bv.y;
        Bs[lk + 2][lrow] = bv.z; Bs[lk + 3][lrow] = bv.w;
        __syncthreads();
        #pragma unroll
        for (int k = 0; k < 16; ++k) {
            float4 a = *(const float4*)&As[k][ty * 4];
            float4 b = *(const float4*)&Bs[k][tx * 4];
            float ar[4] = {a.x, a.y, a.z, a.w};
            float br[4] = {b.x, b.y, b.z, b.w};
            #pragma unroll
            for (int i = 0; i < 4; i++)
                #pragma unroll
                for (int j = 0; j < 4; j++)
                    acc[i][j] = fmaf(ar[i], br[j], acc[i][j]);
        }
    }

    float invc[4];
    #pragma unroll
    for (int i = 0; i < 4; i++) {
        float c = g_counts[m0 + ty * 4 + i];
        invc[i] = 1.f / fmaxf(c, 1.f);
    }
    float bb[4];
    #pragma unroll
    for (int j = 0; j < 4; j++) bb[j] = b1[n0 + tx * 4 + j];

    #pragma unroll
    for (int i = 0; i < 4; i++) {
        float4 o;
        o.x = fmaf(acc[i][0], invc[i], bb[0]);
        o.y = fmaf(acc[i][1], invc[i], bb[1]);
        o.z = fmaf(acc[i][2], invc[i], bb[2]);
        o.w = fmaf(acc[i][3], invc[i], bb[3]);
        *(float4*)&g_h[(size_t)(m0 + ty * 4 + i) * HID + n0 + tx * 4] = o;
    }
}

// ---------------- BN statistics: per-feature sum and sumsq ----------------
__global__ void __launch_bounds__(256)
k_bnstat() {
    const int j = threadIdx.x;
    const int r0 = blockIdx.x * 16;
    float s = 0.f, s2 = 0.f;
    #pragma unroll
    for (int r = 0; r < 16; ++r) {
        float v = g_h[(size_t)(r0 + r) * HID + j];
        s += v;
        s2 = fmaf(v, v, s2);
    }
    atomicAdd(&g_sums[j], s);
    atomicAdd(&g_sumsq[j], s2);
}

// ---------------- BN + ReLU + W2 dot + BCE ----------------
__global__ void __launch_bounds__(256)
k_logits(const float* __restrict__ gamma, const float* __restrict__ beta,
         const float* __restrict__ W2, const float* __restrict__ b2,
         const float* __restrict__ labels, float* __restrict__ out) {
    __shared__ __align__(16) float sc_s[HID];
    __shared__ __align__(16) float sh_s[HID];
    __shared__ __align__(16) float w2_s[HID];

    const int tid = threadIdx.x;
    {
        int j = tid;
        float mean = g_sums[j] * (1.f / BATCH);
        float var = fmaxf(g_sumsq[j] * (1.f / BATCH) - mean * mean, 0.f);
        float rstd = rsqrtf(var + BN_EPS);
        float sc = gamma[j] * rstd;
        sc_s[j] = sc;
        sh_s[j] = fmaf(-mean, sc, beta[j]);
        w2_s[j] = W2[j];
    }
    __syncthreads();

    const int lane = tid & 31;
    const int warp = tid >> 5;
    const int d0 = lane * 8;

    float4 sc0 = *(const float4*)&sc_s[d0];
    float4 sc1 = *(const float4*)&sc_s[d0 + 4];
    float4 sh0 = *(const float4*)&sh_s[d0];
    float4 sh1 = *(const float4*)&sh_s[d0 + 4];
    float4 w0 = *(const float4*)&w2_s[d0];
    float4 w1 = *(const float4*)&w2_s[d0 + 4];
    float bias2 = b2[0];

    float lossacc = 0.f;
    #pragma unroll
    for (int rr = 0; rr < 4; ++rr) {
        int row = blockIdx.x * 32 + warp * 4 + rr;
        const float4* hp = (const float4*)(g_h + (size_t)row * HID);
        float4 v0 = hp[lane * 2];
        float4 v1 = hp[lane * 2 + 1];

        float s = 0.f;
        float x;
        x = fmaxf(fmaf(v0.x, sc0.x, sh0.x), 0.f); s = fmaf(x, w0.x, s);
        x = fmaxf(fmaf(v0.y, sc0.y, sh0.y), 0.f); s = fmaf(x, w0.y, s);
        x = fmaxf(fmaf(v0.z, sc0.z, sh0.z), 0.f); s = fmaf(x, w0.z, s);
        x = fmaxf(fmaf(v0.w, sc0.w, sh0.w), 0.f); s = fmaf(x, w0.w, s);
        x = fmaxf(fmaf(v1.x, sc1.x, sh1.x), 0.f); s = fmaf(x, w1.x, s);
        x = fmaxf(fmaf(v1.y, sc1.y, sh1.y), 0.f); s = fmaf(x, w1.y, s);
        x = fmaxf(fmaf(v1.z, sc1.z, sh1.z), 0.f); s = fmaf(x, w1.z, s);
        x = fmaxf(fmaf(v1.w, sc1.w, sh1.w), 0.f); s = fmaf(x, w1.w, s);

        #pragma unroll
        for (int off = 16; off > 0; off >>= 1)
            s += __shfl_down_sync(0xFFFFFFFFu, s, off);

        if (lane == 0) {
            float logit = s + bias2;
            out[1 + row] = logit;
            float y = labels[row];
            lossacc += fmaxf(logit, 0.f) - logit * y
                       + log1pf(expf(-fabsf(logit)));
        }
    }
    if (lane == 0) atomicAdd(&g_loss, lossacc);
}

__global__ void k_final(float* out) {
    out[0] = g_loss * (1.f / BATCH);
}

// ---------------- launch ----------------
extern "C" void kernel_launch(void* const* d_in, const int* in_sizes, int n_in,
                              void* d_out, int out_size) {
    const int*   tok    = (const int*)d_in[0];
    const int*   seg    = (const int*)d_in[1];
    const float* labels = (const float*)d_in[2];
    const float* emb    = (const float*)d_in[3];
    const float* W1     = (const float*)d_in[4];
    const float* b1     = (const float*)d_in[5];
    const float* gamma  = (const float*)d_in[6];
    const float* beta   = (const float*)d_in[7];
    const float* W2     = (const float*)d_in[8];
    const float* b2     = (const float*)d_in[9];
    float* out = (float*)d_out;

    k_detect<<<1, 64>>>(tok);
    k_init<<<1024, 256>>>();
    k_gather<<<N_TOK / (TOK_PER_WARP * GATHER_WARPS), GATHER_WARPS * 32>>>(tok, seg, emb);
    k_gemm<<<dim3(HID / 64, BATCH / 64), 256>>>(W1, b1);
    k_bnstat<<<BATCH / 16, 256>>>();
    k_logits<<<BATCH / 32, 256>>>(gamma, beta, W2, b2, labels, out);
    k_final<<<1, 1>>>(out);
}

// round 3
// speedup vs baseline: 1.1737x; 1.1737x over previous
#include <cuda_runtime.h>
#include <cuda_fp16.h>
#include <cuda_bf16.h>
#include <cstdint>

#define VOCAB   100000
#define N_TOK   819200
#define BATCH   4096
#define HID     256
#define BN_EPS  1e-5f

// ---------------- device scratch (no allocations allowed) ----------------
__device__ __align__(16) __half g_emb_h[(size_t)VOCAB * HID];  // 51.2 MB fp16 table
__device__ __align__(16) float g_segsum[BATCH * HID];          // 4 MB
__device__ __align__(16) float g_h[BATCH * HID];               // 4 MB
__device__ __align__(16) float g_counts[BATCH];
__device__ __align__(16) float g_sums[HID];
__device__ __align__(16) float g_sumsq[HID];
__device__ float g_loss;
__device__ int   g_nz;     // nonzero odd words => int32 ids
__device__ int   g_done;   // ticket for loss finalization

// ---------------- prep: fp32->fp16 table convert + zero accum + detect ----
// grid = 12500 blocks x 256 threads; thread converts 8 elements (exact cover).
__global__ void __launch_bounds__(256)
k_prep(const float* __restrict__ emb, const int* __restrict__ tok) {
    const int bid = blockIdx.x, tid = threadIdx.x;
    // table conversion
    size_t idx = ((size_t)bid * 256 + tid) * 8;
    const float4* src = (const float4*)(emb + idx);
    float4 v0 = src[0];
    float4 v1 = src[1];
    uint4 pack;
    __half2 h;
    h = __floats2half2_rn(v0.x, v0.y); pack.x = *(uint32_t*)&h;
    h = __floats2half2_rn(v0.z, v0.w); pack.y = *(uint32_t*)&h;
    h = __floats2half2_rn(v1.x, v1.y); pack.z = *(uint32_t*)&h;
    h = __floats2half2_rn(v1.z, v1.w); pack.w = *(uint32_t*)&h;
    *(uint4*)(g_emb_h + idx) = pack;

    if (bid < 1024) {
        // zero segsum: 1024 floats per block
        *(float4*)&g_segsum[bid * 1024 + tid * 4] = make_float4(0.f, 0.f, 0.f, 0.f);
    } else if (bid == 1024) {
        float4 z = make_float4(0.f, 0.f, 0.f, 0.f);
        #pragma unroll
        for (int i = 0; i < 4; i++)
            *(float4*)&g_counts[tid * 16 + i * 4] = z;
        g_sums[tid] = 0.f;
        g_sumsq[tid] = 0.f;
        if (tid == 0) g_loss = 0.f;
    } else if (bid == 1025 && tid < 64) {
        if (tok[2 * tid + 1] != 0) atomicOr(&g_nz, 1);
    }
}

// ---------------- gather + segment sum (fp16 table, fp32 accumulate) ------
#define TOK_PER_WARP 64
#define GATHER_WARPS 8

__device__ __forceinline__ void flush_run(int seg, const float* a, int runlen, int lane) {
    float* dst = g_segsum + (size_t)seg * HID + lane * 8;
    asm volatile("red.global.add.v4.f32 [%0], {%1,%2,%3,%4};"
                 :: "l"(dst), "f"(a[0]), "f"(a[1]), "f"(a[2]), "f"(a[3]) : "memory");
    asm volatile("red.global.add.v4.f32 [%0], {%1,%2,%3,%4};"
                 :: "l"(dst + 4), "f"(a[4]), "f"(a[5]), "f"(a[6]), "f"(a[7]) : "memory");
    if (lane == 0) atomicAdd(&g_counts[seg], (float)runlen);
}

__global__ void __launch_bounds__(GATHER_WARPS * 32)
k_gather(const int* __restrict__ tok, const int* __restrict__ seg) {
    const int stride = g_nz ? 1 : 2;
    const int lane = threadIdx.x & 31;
    const int warp_id = blockIdx.x * GATHER_WARPS + (threadIdx.x >> 5);
    const int t0 = warp_id * TOK_PER_WARP;

    float a[8];
    #pragma unroll
    for (int i = 0; i < 8; i++) a[i] = 0.f;
    int cur = seg[(size_t)t0 * stride];
    int runlen = 0;

    const size_t lane_off = lane * 8;

    #pragma unroll 4
    for (int t = t0; t < t0 + TOK_PER_WARP; ++t) {
        int s = seg[(size_t)t * stride];
        if (s != cur) {
            flush_run(cur, a, runlen, lane);
            #pragma unroll
            for (int i = 0; i < 8; i++) a[i] = 0.f;
            runlen = 0;
            cur = s;
        }
        int id = tok[(size_t)t * stride];
        uint4 v = *(const uint4*)(g_emb_h + (size_t)id * HID + lane_off);
        const __half2* hp = (const __half2*)&v;
        float2 f;
        f = __half22float2(hp[0]); a[0] += f.x; a[1] += f.y;
        f = __half22float2(hp[1]); a[2] += f.x; a[3] += f.y;
        f = __half22float2(hp[2]); a[4] += f.x; a[5] += f.y;
        f = __half22float2(hp[3]); a[6] += f.x; a[7] += f.y;
        ++runlen;
    }
    flush_run(cur, a, runlen, lane);
}

// ---------------- GEMM: h = (segsum*invc) @ W1^T + b1 (split-bf16 mma) ----
// Block tile 128x64, BK=32, 256 threads (8 warps: 4 M x 2 N, warp tile 32x32).
// D = Ah@Bh + Ah@Bl + Al@Bh  (Al@Bl dropped: ~2^-18 relative).
#define BM 128
#define BN 64
#define BK 32
#define KPAD 40   // halves; 80B pitch -> 16B-aligned rows, ldmatrix conflict-free

__device__ __forceinline__ void ldsm4(uint32_t& r0, uint32_t& r1, uint32_t& r2,
                                      uint32_t& r3, const void* p) {
    uint32_t addr = (uint32_t)__cvta_generic_to_shared(p);
    asm volatile("ldmatrix.sync.aligned.m8n8.x4.shared.b16 {%0,%1,%2,%3}, [%4];"
                 : "=r"(r0), "=r"(r1), "=r"(r2), "=r"(r3) : "r"(addr));
}

__device__ __forceinline__ void mma16816(float* c, uint32_t a0, uint32_t a1,
                                         uint32_t a2, uint32_t a3,
                                         uint32_t b0, uint32_t b1) {
    asm volatile(
        "mma.sync.aligned.m16n8k16.row.col.f32.bf16.bf16.f32 "
        "{%0,%1,%2,%3}, {%4,%5,%6,%7}, {%8,%9}, {%0,%1,%2,%3};"
        : "+f"(c[0]), "+f"(c[1]), "+f"(c[2]), "+f"(c[3])
        : "r"(a0), "r"(a1), "r"(a2), "r"(a3), "r"(b0), "r"(b1));
}

__device__ __forceinline__ uint32_t pack_bf2(float x, float y) {
    __nv_bfloat162 t = __floats2bfloat162_rn(x, y);
    return *(uint32_t*)&t;
}

__global__ void __launch_bounds__(256)
k_gemm(const float* __restrict__ W1, const float* __restrict__ b1) {
    __shared__ __nv_bfloat16 sAh[BM][KPAD], sAl[BM][KPAD];
    __shared__ __nv_bfloat16 sBh[BN][KPAD], sBl[BN][KPAD];

    const int tid = threadIdx.x;
    const int m0 = blockIdx.y * BM;
    const int n0 = blockIdx.x * BN;

    // load mapping
    const int ar = tid >> 1;           // 0..127
    const int ak = (tid & 1) * 16;     // 0 or 16
    const int br = tid >> 2;           // 0..63
    const int bk = (tid & 3) * 8;      // 0,8,16,24

    const float invc = 1.f / fmaxf(g_counts[m0 + ar], 1.f);

    const int warp = tid >> 5, lane = tid & 31;
    const int wm0 = (warp >> 1) * 32;
    const int wn0 = (warp & 1) * 32;
    const int q = lane >> 3, r = lane & 7;

    float acc[2][4][4];
    #pragma unroll
    for (int i = 0; i < 2; i++)
        #pragma unroll
        for (int j = 0; j < 4; j++)
            #pragma unroll
            for (int k = 0; k < 4; k++) acc[i][j][k] = 0.f;

    float aR[16], bR[8];

    // prologue: load k0 = 0
    #pragma unroll
    for (int i = 0; i < 4; i++)
        *(float4*)&aR[i * 4] = *(const float4*)&g_segsum[(size_t)(m0 + ar) * HID + ak + i * 4];
    #pragma unroll
    for (int i = 0; i < 2; i++)
        *(float4*)&bR[i * 4] = *(const float4*)&W1[(size_t)(n0 + br) * HID + bk + i * 4];

    for (int k0 = 0; k0 < HID; k0 += BK) {
        // store staged regs -> smem with hi/lo split
        #pragma unroll
        for (int i = 0; i < 16; i += 2) {
            float x0 = aR[i] * invc, x1 = aR[i + 1] * invc;
            __nv_bfloat16 h0 = __float2bfloat16(x0), h1 = __float2bfloat16(x1);
            float l0 = x0 - __bfloat162float(h0), l1 = x1 - __bfloat162float(h1);
            *(uint32_t*)&sAh[ar][ak + i] = ((uint32_t)*(uint16_t*)&h1 << 16) | *(uint16_t*)&h0;
            *(uint32_t*)&sAl[ar][ak + i] = pack_bf2(l0, l1);
        }
        #pragma unroll
        for (int i = 0; i < 8; i += 2) {
            float x0 = bR[i], x1 = bR[i + 1];
            __nv_bfloat16 h0 = __float2bfloat16(x0), h1 = __float2bfloat16(x1);
            float l0 = x0 - __bfloat162float(h0), l1 = x1 - __bfloat162float(h1);
            *(uint32_t*)&sBh[br][bk + i] = ((uint32_t)*(uint16_t*)&h1 << 16) | *(uint16_t*)&h0;
            *(uint32_t*)&sBl[br][bk + i] = pack_bf2(l0, l1);
        }
        __syncthreads();

        // prefetch next stage
        const int kn = k0 + BK;
        if (kn < HID) {
            #pragma unroll
            for (int i = 0; i < 4; i++)
                *(float4*)&aR[i * 4] = *(const float4*)&g_segsum[(size_t)(m0 + ar) * HID + kn + ak + i * 4];
            #pragma unroll
            for (int i = 0; i < 2; i++)
                *(float4*)&bR[i * 4] = *(const float4*)&W1[(size_t)(n0 + br) * HID + kn + bk + i * 4];
        }

        // compute 2 x k16
        #pragma unroll
        for (int kk = 0; kk < BK; kk += 16) {
            uint32_t ah[2][4], al[2][4], bh[2][4], bl[2][4];
            #pragma unroll
            for (int mt = 0; mt < 2; mt++) {
                const int row = wm0 + mt * 16 + (q & 1) * 8 + r;
                const int col = kk + (q >> 1) * 8;
                ldsm4(ah[mt][0], ah[mt][1], ah[mt][2], ah[mt][3], &sAh[row][col]);
                ldsm4(al[mt][0], al[mt][1], al[mt][2], al[mt][3], &sAl[row][col]);
            }
            #pragma unroll
            for (int p = 0; p < 2; p++) {
                const int row = wn0 + p * 16 + (q >> 1) * 8 + r;
                const int col = kk + (q & 1) * 8;
                ldsm4(bh[p][0], bh[p][1], bh[p][2], bh[p][3], &sBh[row][col]);
                ldsm4(bl[p][0], bl[p][1], bl[p][2], bl[p][3], &sBl[row][col]);
            }
            #pragma unroll
            for (int mt = 0; mt < 2; mt++)
                #pragma unroll
                for (int nt = 0; nt < 4; nt++) {
                    uint32_t B0h = bh[nt >> 1][(nt & 1) * 2];
                    uint32_t B1h = bh[nt >> 1][(nt & 1) * 2 + 1];
                    uint32_t B0l = bl[nt >> 1][(nt & 1) * 2];
                    uint32_t B1l = bl[nt >> 1][(nt & 1) * 2 + 1];
                    mma16816(acc[mt][nt], ah[mt][0], ah[mt][1], ah[mt][2], ah[mt][3], B0h, B1h);
                    mma16816(acc[mt][nt], ah[mt][0], ah[mt][1], ah[mt][2], ah[mt][3], B0l, B1l);
                    mma16816(acc[mt][nt], al[mt][0], al[mt][1], al[mt][2], al[mt][3], B0h, B1h);
                }
        }
        __syncthreads();
    }

    // epilogue: + b1, write g_h
    #pragma unroll
    for (int mt = 0; mt < 2; mt++) {
        const int row = m0 + wm0 + mt * 16 + (lane >> 2);
        #pragma unroll
        for (int nt = 0; nt < 4; nt++) {
            const int col = n0 + wn0 + nt * 8 + (lane & 3) * 2;
            float bx = b1[col], by = b1[col + 1];
            float2 o0 = make_float2(acc[mt][nt][0] + bx, acc[mt][nt][1] + by);
            float2 o1 = make_float2(acc[mt][nt][2] + bx, acc[mt][nt][3] + by);
            *(float2*)&g_h[(size_t)row * HID + col] = o0;
            *(float2*)&g_h[(size_t)(row + 8) * HID + col] = o1;
        }
    }
}

// ---------------- BN statistics ----------------
__global__ void __launch_bounds__(256)
k_bnstat() {
    const int j = threadIdx.x;
    const int r0 = blockIdx.x * 16;
    float s = 0.f, s2 = 0.f;
    #pragma unroll
    for (int r = 0; r < 16; ++r) {
        float v = g_h[(size_t)(r0 + r) * HID + j];
        s += v;
        s2 = fmaf(v, v, s2);
    }
    atomicAdd(&g_sums[j], s);
    atomicAdd(&g_sumsq[j], s2);
}

// ---------------- BN + ReLU + W2 dot + BCE + loss finalize ----------------
__global__ void __launch_bounds__(256)
k_logits(const float* __restrict__ gamma, const float* __restrict__ beta,
         const float* __restrict__ W2, const float* __restrict__ b2,
         const float* __restrict__ labels, float* __restrict__ out) {
    __shared__ __align__(16) float sc_s[HID];
    __shared__ __align__(16) float sh_s[HID];
    __shared__ __align__(16) float w2_s[HID];

    const int tid = threadIdx.x;
    {
        int j = tid;
        float mean = g_sums[j] * (1.f / BATCH);
        float var = fmaxf(g_sumsq[j] * (1.f / BATCH) - mean * mean, 0.f);
        float rstd = rsqrtf(var + BN_EPS);
        float sc = gamma[j] * rstd;
        sc_s[j] = sc;
        sh_s[j] = fmaf(-mean, sc, beta[j]);
        w2_s[j] = W2[j];
    }
    __syncthreads();

    const int lane = tid & 31;
    const int warp = tid >> 5;
    const int d0 = lane * 8;

    float4 sc0 = *(const float4*)&sc_s[d0];
    float4 sc1 = *(const float4*)&sc_s[d0 + 4];
    float4 sh0 = *(const float4*)&sh_s[d0];
    float4 sh1 = *(const float4*)&sh_s[d0 + 4];
    float4 w0 = *(const float4*)&w2_s[d0];
    float4 w1 = *(const float4*)&w2_s[d0 + 4];
    float bias2 = b2[0];

    float lossacc = 0.f;
    #pragma unroll
    for (int rr = 0; rr < 4; ++rr) {
        int row = blockIdx.x * 32 + warp * 4 + rr;
        const float4* hp = (const float4*)(g_h + (size_t)row * HID);
        float4 v0 = hp[lane * 2];
        float4 v1 = hp[lane * 2 + 1];

        float s = 0.f, x;
        x = fmaxf(fmaf(v0.x, sc0.x, sh0.x), 0.f); s = fmaf(x, w0.x, s);
        x = fmaxf(fmaf(v0.y, sc0.y, sh0.y), 0.f); s = fmaf(x, w0.y, s);
        x = fmaxf(fmaf(v0.z, sc0.z, sh0.z), 0.f); s = fmaf(x, w0.z, s);
        x = fmaxf(fmaf(v0.w, sc0.w, sh0.w), 0.f); s = fmaf(x, w0.w, s);
        x = fmaxf(fmaf(v1.x, sc1.x, sh1.x), 0.f); s = fmaf(x, w1.x, s);
        x = fmaxf(fmaf(v1.y, sc1.y, sh1.y), 0.f); s = fmaf(x, w1.y, s);
        x = fmaxf(fmaf(v1.z, sc1.z, sh1.z), 0.f); s = fmaf(x, w1.z, s);
        x = fmaxf(fmaf(v1.w, sc1.w, sh1.w), 0.f); s = fmaf(x, w1.w, s);

        #pragma unroll
        for (int off = 16; off > 0; off >>= 1)
            s += __shfl_down_sync(0xFFFFFFFFu, s, off);

        if (lane == 0) {
            float logit = s + bias2;
            out[1 + row] = logit;
            float y = labels[row];
            lossacc += fmaxf(logit, 0.f) - logit * y + log1pf(expf(-fabsf(logit)));
        }
    }
    if (lane == 0) atomicAdd(&g_loss, lossacc);

    __syncthreads();
    if (tid == 0) {
        __threadfence();
        int old = atomicAdd(&g_done, 1);
        if (old == (int)gridDim.x - 1) {
            g_done = 0;
            float L = atomicAdd(&g_loss, 0.f);
            out[0] = L * (1.f / BATCH);
        }
    }
}

// ---------------- launch ----------------
extern "C" void kernel_launch(void* const* d_in, const int* in_sizes, int n_in,
                              void* d_out, int out_size) {
    const int*   tok    = (const int*)d_in[0];
    const int*   seg    = (const int*)d_in[1];
    const float* labels = (const float*)d_in[2];
    const float* emb    = (const float*)d_in[3];
    const float* W1     = (const float*)d_in[4];
    const float* b1     = (const float*)d_in[5];
    const float* gamma  = (const float*)d_in[6];
    const float* beta   = (const float*)d_in[7];
    const float* W2     = (const float*)d_in[8];
    const float* b2     = (const float*)d_in[9];
    float* out = (float*)d_out;

    k_prep<<<(VOCAB * HID) / (256 * 8), 256>>>(emb, tok);   // 12500 blocks
    k_gather<<<N_TOK / (TOK_PER_WARP * GATHER_WARPS), GATHER_WARPS * 32>>>(tok, seg);
    k_gemm<<<dim3(HID / BN, BATCH / BM), 256>>>(W1, b1);
    k_bnstat<<<BATCH / 16, 256>>>();
    k_logits<<<BATCH / 32, 256>>>(gamma, beta, W2, b2, labels, out);
}

// round 4
// speedup vs baseline: 1.2460x; 1.0616x over previous
#include <cuda_runtime.h>
#include <cuda_fp16.h>
#include <cuda_bf16.h>
#include <cstdint>

#define VOCAB   100000
#define N_TOK   819200
#define BATCH   4096
#define HID     256
#define BN_EPS  1e-5f

// ---------------- device scratch (no allocations allowed) ----------------
__device__ __align__(16) __half g_emb_h[(size_t)VOCAB * HID];  // 51.2 MB fp16 table
__device__ __align__(16) float g_segsum[BATCH * HID];          // 4 MB
__device__ __align__(16) float g_h[BATCH * HID];               // 4 MB
__device__ __align__(16) float g_counts[BATCH];
__device__ __align__(16) float g_sums[HID];
__device__ __align__(16) float g_sumsq[HID];
__device__ float g_loss;
__device__ int   g_nz;     // nonzero odd words => int32 ids
__device__ int   g_done;   // ticket for loss finalization

// ---------------- prep: fp32->fp16 table convert + zero accum + detect ----
__global__ void __launch_bounds__(256)
k_prep(const float* __restrict__ emb, const int* __restrict__ tok) {
    const int bid = blockIdx.x, tid = threadIdx.x;
    size_t idx = ((size_t)bid * 256 + tid) * 8;
    const float4* src = (const float4*)(emb + idx);
    float4 v0 = src[0];
    float4 v1 = src[1];
    uint4 pack;
    __half2 h;
    h = __floats2half2_rn(v0.x, v0.y); pack.x = *(uint32_t*)&h;
    h = __floats2half2_rn(v0.z, v0.w); pack.y = *(uint32_t*)&h;
    h = __floats2half2_rn(v1.x, v1.y); pack.z = *(uint32_t*)&h;
    h = __floats2half2_rn(v1.z, v1.w); pack.w = *(uint32_t*)&h;
    *(uint4*)(g_emb_h + idx) = pack;

    if (bid < 1024) {
        *(float4*)&g_segsum[bid * 1024 + tid * 4] = make_float4(0.f, 0.f, 0.f, 0.f);
    } else if (bid == 1024) {
        float4 z = make_float4(0.f, 0.f, 0.f, 0.f);
        #pragma unroll
        for (int i = 0; i < 4; i++)
            *(float4*)&g_counts[tid * 16 + i * 4] = z;
        g_sums[tid] = 0.f;
        g_sumsq[tid] = 0.f;
        if (tid == 0) g_loss = 0.f;
    } else if (bid == 1025 && tid < 64) {
        if (tok[2 * tid + 1] != 0) atomicOr(&g_nz, 1);
    }
}

// ---------------- gather + segment sum (fp16 table, fp32 accumulate) ------
#define TOK_PER_WARP 64
#define GATHER_WARPS 8

__device__ __forceinline__ void flush_run(int seg, const float* a, int runlen, int lane) {
    float* dst = g_segsum + (size_t)seg * HID + lane * 8;
    asm volatile("red.global.add.v4.f32 [%0], {%1,%2,%3,%4};"
                 :: "l"(dst), "f"(a[0]), "f"(a[1]), "f"(a[2]), "f"(a[3]) : "memory");
    asm volatile("red.global.add.v4.f32 [%0], {%1,%2,%3,%4};"
                 :: "l"(dst + 4), "f"(a[4]), "f"(a[5]), "f"(a[6]), "f"(a[7]) : "memory");
    if (lane == 0) atomicAdd(&g_counts[seg], (float)runlen);
}

__global__ void __launch_bounds__(GATHER_WARPS * 32)
k_gather(const int* __restrict__ tok, const int* __restrict__ seg) {
    const int stride = g_nz ? 1 : 2;
    const int lane = threadIdx.x & 31;
    const int warp_id = blockIdx.x * GATHER_WARPS + (threadIdx.x >> 5);
    const int t0 = warp_id * TOK_PER_WARP;

    float a[8];
    #pragma unroll
    for (int i = 0; i < 8; i++) a[i] = 0.f;
    int cur = seg[(size_t)t0 * stride];
    int runlen = 0;

    const size_t lane_off = lane * 8;

    #pragma unroll 4
    for (int t = t0; t < t0 + TOK_PER_WARP; ++t) {
        int s = seg[(size_t)t * stride];
        if (s != cur) {
            flush_run(cur, a, runlen, lane);
            #pragma unroll
            for (int i = 0; i < 8; i++) a[i] = 0.f;
            runlen = 0;
            cur = s;
        }
        int id = tok[(size_t)t * stride];
        uint4 v = *(const uint4*)(g_emb_h + (size_t)id * HID + lane_off);
        const __half2* hp = (const __half2*)&v;
        float2 f;
        f = __half22float2(hp[0]); a[0] += f.x; a[1] += f.y;
        f = __half22float2(hp[1]); a[2] += f.x; a[3] += f.y;
        f = __half22float2(hp[2]); a[4] += f.x; a[5] += f.y;
        f = __half22float2(hp[3]); a[6] += f.x; a[7] += f.y;
        ++runlen;
    }
    flush_run(cur, a, runlen, lane);
}

// ---------------- GEMM: h = (segsum*invc) @ W1^T + b1 (split-bf16 mma) ----
// Block tile 128x64, BK=32, 256 threads (8 warps: 4 M x 2 N, warp tile 32x32).
// D = Ah@Bh + Ah@Bl + Al@Bh. BN statistics fused into the epilogue.
#define BM 128
#define BN 64
#define BK 32
#define KPAD 40

__device__ __forceinline__ void ldsm4(uint32_t& r0, uint32_t& r1, uint32_t& r2,
                                      uint32_t& r3, const void* p) {
    uint32_t addr = (uint32_t)__cvta_generic_to_shared(p);
    asm volatile("ldmatrix.sync.aligned.m8n8.x4.shared.b16 {%0,%1,%2,%3}, [%4];"
                 : "=r"(r0), "=r"(r1), "=r"(r2), "=r"(r3) : "r"(addr));
}

__device__ __forceinline__ void mma16816(float* c, uint32_t a0, uint32_t a1,
                                         uint32_t a2, uint32_t a3,
                                         uint32_t b0, uint32_t b1) {
    asm volatile(
        "mma.sync.aligned.m16n8k16.row.col.f32.bf16.bf16.f32 "
        "{%0,%1,%2,%3}, {%4,%5,%6,%7}, {%8,%9}, {%0,%1,%2,%3};"
        : "+f"(c[0]), "+f"(c[1]), "+f"(c[2]), "+f"(c[3])
        : "r"(a0), "r"(a1), "r"(a2), "r"(a3), "r"(b0), "r"(b1));
}

__device__ __forceinline__ uint32_t pack_bf2(float x, float y) {
    __nv_bfloat162 t = __floats2bfloat162_rn(x, y);
    return *(uint32_t*)&t;
}

__global__ void __launch_bounds__(256)
k_gemm(const float* __restrict__ W1, const float* __restrict__ b1) {
    __shared__ __nv_bfloat16 sAh[BM][KPAD], sAl[BM][KPAD];
    __shared__ __nv_bfloat16 sBh[BN][KPAD], sBl[BN][KPAD];
    __shared__ float s_stat[2][BN];

    const int tid = threadIdx.x;
    const int m0 = blockIdx.y * BM;
    const int n0 = blockIdx.x * BN;

    if (tid < BN) { s_stat[0][tid] = 0.f; s_stat[1][tid] = 0.f; }

    const int ar = tid >> 1;
    const int ak = (tid & 1) * 16;
    const int br = tid >> 2;
    const int bk = (tid & 3) * 8;

    const float invc = 1.f / fmaxf(g_counts[m0 + ar], 1.f);

    const int warp = tid >> 5, lane = tid & 31;
    const int wm0 = (warp >> 1) * 32;
    const int wn0 = (warp & 1) * 32;
    const int q = lane >> 3, r = lane & 7;

    float acc[2][4][4];
    #pragma unroll
    for (int i = 0; i < 2; i++)
        #pragma unroll
        for (int j = 0; j < 4; j++)
            #pragma unroll
            for (int k = 0; k < 4; k++) acc[i][j][k] = 0.f;

    float aR[16], bR[8];

    #pragma unroll
    for (int i = 0; i < 4; i++)
        *(float4*)&aR[i * 4] = *(const float4*)&g_segsum[(size_t)(m0 + ar) * HID + ak + i * 4];
    #pragma unroll
    for (int i = 0; i < 2; i++)
        *(float4*)&bR[i * 4] = *(const float4*)&W1[(size_t)(n0 + br) * HID + bk + i * 4];

    for (int k0 = 0; k0 < HID; k0 += BK) {
        #pragma unroll
        for (int i = 0; i < 16; i += 2) {
            float x0 = aR[i] * invc, x1 = aR[i + 1] * invc;
            __nv_bfloat16 h0 = __float2bfloat16(x0), h1 = __float2bfloat16(x1);
            float l0 = x0 - __bfloat162float(h0), l1 = x1 - __bfloat162float(h1);
            *(uint32_t*)&sAh[ar][ak + i] = ((uint32_t)*(uint16_t*)&h1 << 16) | *(uint16_t*)&h0;
            *(uint32_t*)&sAl[ar][ak + i] = pack_bf2(l0, l1);
        }
        #pragma unroll
        for (int i = 0; i < 8; i += 2) {
            float x0 = bR[i], x1 = bR[i + 1];
            __nv_bfloat16 h0 = __float2bfloat16(x0), h1 = __float2bfloat16(x1);
            float l0 = x0 - __bfloat162float(h0), l1 = x1 - __bfloat162float(h1);
            *(uint32_t*)&sBh[br][bk + i] = ((uint32_t)*(uint16_t*)&h1 << 16) | *(uint16_t*)&h0;
            *(uint32_t*)&sBl[br][bk + i] = pack_bf2(l0, l1);
        }
        __syncthreads();

        const int kn = k0 + BK;
        if (kn < HID) {
            #pragma unroll
            for (int i = 0; i < 4; i++)
                *(float4*)&aR[i * 4] = *(const float4*)&g_segsum[(size_t)(m0 + ar) * HID + kn + ak + i * 4];
            #pragma unroll
            for (int i = 0; i < 2; i++)
                *(float4*)&bR[i * 4] = *(const float4*)&W1[(size_t)(n0 + br) * HID + kn + bk + i * 4];
        }

        #pragma unroll
        for (int kk = 0; kk < BK; kk += 16) {
            uint32_t ah[2][4], al[2][4], bh[2][4], bl[2][4];
            #pragma unroll
            for (int mt = 0; mt < 2; mt++) {
                const int row = wm0 + mt * 16 + (q & 1) * 8 + r;
                const int col = kk + (q >> 1) * 8;
                ldsm4(ah[mt][0], ah[mt][1], ah[mt][2], ah[mt][3], &sAh[row][col]);
                ldsm4(al[mt][0], al[mt][1], al[mt][2], al[mt][3], &sAl[row][col]);
            }
            #pragma unroll
            for (int p = 0; p < 2; p++) {
                const int row = wn0 + p * 16 + (q >> 1) * 8 + r;
                const int col = kk + (q & 1) * 8;
                ldsm4(bh[p][0], bh[p][1], bh[p][2], bh[p][3], &sBh[row][col]);
                ldsm4(bl[p][0], bl[p][1], bl[p][2], bl[p][3], &sBl[row][col]);
            }
            #pragma unroll
            for (int mt = 0; mt < 2; mt++)
                #pragma unroll
                for (int nt = 0; nt < 4; nt++) {
                    uint32_t B0h = bh[nt >> 1][(nt & 1) * 2];
                    uint32_t B1h = bh[nt >> 1][(nt & 1) * 2 + 1];
                    uint32_t B0l = bl[nt >> 1][(nt & 1) * 2];
                    uint32_t B1l = bl[nt >> 1][(nt & 1) * 2 + 1];
                    mma16816(acc[mt][nt], ah[mt][0], ah[mt][1], ah[mt][2], ah[mt][3], B0h, B1h);
                    mma16816(acc[mt][nt], ah[mt][0], ah[mt][1], ah[mt][2], ah[mt][3], B0l, B1l);
                    mma16816(acc[mt][nt], al[mt][0], al[mt][1], al[mt][2], al[mt][3], B0h, B1h);
                }
        }
        __syncthreads();
    }

    // epilogue: + b1, write g_h, fused BN statistics
    #pragma unroll
    for (int nt = 0; nt < 4; nt++) {
        const int col = n0 + wn0 + nt * 8 + (lane & 3) * 2;
        const float bx = b1[col], by = b1[col + 1];
        float sx = 0.f, sy = 0.f, qx = 0.f, qy = 0.f;
        #pragma unroll
        for (int mt = 0; mt < 2; mt++) {
            const int row = m0 + wm0 + mt * 16 + (lane >> 2);
            float ox0 = acc[mt][nt][0] + bx, oy0 = acc[mt][nt][1] + by;
            float ox1 = acc[mt][nt][2] + bx, oy1 = acc[mt][nt][3] + by;
            *(float2*)&g_h[(size_t)row * HID + col] = make_float2(ox0, oy0);
            *(float2*)&g_h[(size_t)(row + 8) * HID + col] = make_float2(ox1, oy1);
            sx += ox0 + ox1;           sy += oy0 + oy1;
            qx = fmaf(ox0, ox0, qx);   qx = fmaf(ox1, ox1, qx);
            qy = fmaf(oy0, oy0, qy);   qy = fmaf(oy1, oy1, qy);
        }
        // reduce across lanes sharing (lane & 3): offsets 16, 8, 4
        #pragma unroll
        for (int off = 16; off >= 4; off >>= 1) {
            sx += __shfl_down_sync(0xFFFFFFFFu, sx, off);
            sy += __shfl_down_sync(0xFFFFFFFFu, sy, off);
            qx += __shfl_down_sync(0xFFFFFFFFu, qx, off);
            qy += __shfl_down_sync(0xFFFFFFFFu, qy, off);
        }
        if (lane < 4) {
            const int c = wn0 + nt * 8 + lane * 2;
            atomicAdd(&s_stat[0][c], sx);
            atomicAdd(&s_stat[0][c + 1], sy);
            atomicAdd(&s_stat[1][c], qx);
            atomicAdd(&s_stat[1][c + 1], qy);
        }
    }
    __syncthreads();
    if (tid < BN) {
        atomicAdd(&g_sums[n0 + tid], s_stat[0][tid]);
        atomicAdd(&g_sumsq[n0 + tid], s_stat[1][tid]);
    }
}

// ---------------- BN + ReLU + W2 dot + BCE + loss finalize ----------------
// 512 blocks x 256 threads; one row per warp; block-local loss reduction.
__global__ void __launch_bounds__(256)
k_logits(const float* __restrict__ gamma, const float* __restrict__ beta,
         const float* __restrict__ W2, const float* __restrict__ b2,
         const float* __restrict__ labels, float* __restrict__ out) {
    __shared__ __align__(16) float sc_s[HID];
    __shared__ __align__(16) float sh_s[HID];
    __shared__ __align__(16) float w2_s[HID];
    __shared__ float s_loss;

    const int tid = threadIdx.x;
    if (tid == 0) s_loss = 0.f;
    {
        int j = tid;
        float mean = g_sums[j] * (1.f / BATCH);
        float var = fmaxf(g_sumsq[j] * (1.f / BATCH) - mean * mean, 0.f);
        float rstd = rsqrtf(var + BN_EPS);
        float sc = gamma[j] * rstd;
        sc_s[j] = sc;
        sh_s[j] = fmaf(-mean, sc, beta[j]);
        w2_s[j] = W2[j];
    }
    __syncthreads();

    const int lane = tid & 31;
    const int warp = tid >> 5;
    const int d0 = lane * 8;

    float4 sc0 = *(const float4*)&sc_s[d0];
    float4 sc1 = *(const float4*)&sc_s[d0 + 4];
    float4 sh0 = *(const float4*)&sh_s[d0];
    float4 sh1 = *(const float4*)&sh_s[d0 + 4];
    float4 w0 = *(const float4*)&w2_s[d0];
    float4 w1 = *(const float4*)&w2_s[d0 + 4];
    float bias2 = b2[0];

    const int row = blockIdx.x * 8 + warp;
    const float4* hp = (const float4*)(g_h + (size_t)row * HID);
    float4 v0 = hp[lane * 2];
    float4 v1 = hp[lane * 2 + 1];

    float s = 0.f, x;
    x = fmaxf(fmaf(v0.x, sc0.x, sh0.x), 0.f); s = fmaf(x, w0.x, s);
    x = fmaxf(fmaf(v0.y, sc0.y, sh0.y), 0.f); s = fmaf(x, w0.y, s);
    x = fmaxf(fmaf(v0.z, sc0.z, sh0.z), 0.f); s = fmaf(x, w0.z, s);
    x = fmaxf(fmaf(v0.w, sc0.w, sh0.w), 0.f); s = fmaf(x, w0.w, s);
    x = fmaxf(fmaf(v1.x, sc1.x, sh1.x), 0.f); s = fmaf(x, w1.x, s);
    x = fmaxf(fmaf(v1.y, sc1.y, sh1.y), 0.f); s = fmaf(x, w1.y, s);
    x = fmaxf(fmaf(v1.z, sc1.z, sh1.z), 0.f); s = fmaf(x, w1.z, s);
    x = fmaxf(fmaf(v1.w, sc1.w, sh1.w), 0.f); s = fmaf(x, w1.w, s);

    #pragma unroll
    for (int off = 16; off > 0; off >>= 1)
        s += __shfl_down_sync(0xFFFFFFFFu, s, off);

    if (lane == 0) {
        float logit = s + bias2;
        out[1 + row] = logit;
        float y = labels[row];
        float l = fmaxf(logit, 0.f) - logit * y + log1pf(expf(-fabsf(logit)));
        atomicAdd(&s_loss, l);
    }
    __syncthreads();
    if (tid == 0) {
        atomicAdd(&g_loss, s_loss);
        __threadfence();
        int old = atomicAdd(&g_done, 1);
        if (old == (int)gridDim.x - 1) {
            g_done = 0;
            float L = atomicAdd(&g_loss, 0.f);
            out[0] = L * (1.f / BATCH);
        }
    }
}

// ---------------- launch ----------------
extern "C" void kernel_launch(void* const* d_in, const int* in_sizes, int n_in,
                              void* d_out, int out_size) {
    const int*   tok    = (const int*)d_in[0];
    const int*   seg    = (const int*)d_in[1];
    const float* labels = (const float*)d_in[2];
    const float* emb    = (const float*)d_in[3];
    const float* W1     = (const float*)d_in[4];
    const float* b1     = (const float*)d_in[5];
    const float* gamma  = (const float*)d_in[6];
    const float* beta   = (const float*)d_in[7];
    const float* W2     = (const float*)d_in[8];
    const float* b2     = (const float*)d_in[9];
    float* out = (float*)d_out;

    k_prep<<<(VOCAB * HID) / (256 * 8), 256>>>(emb, tok);
    k_gather<<<N_TOK / (TOK_PER_WARP * GATHER_WARPS), GATHER_WARPS * 32>>>(tok, seg);
    k_gemm<<<dim3(HID / BN, BATCH / BM), 256>>>(W1, b1);
    k_logits<<<BATCH / 8, 256>>>(gamma, beta, W2, b2, labels, out);
}

// round 5
// speedup vs baseline: 1.4521x; 1.1654x over previous
#include <cuda_runtime.h>
#include <cuda_fp16.h>
#include <cuda_bf16.h>
#include <cstdint>

#define VOCAB   100000
#define N_TOK   819200
#define BATCH   4096
#define HID     256
#define BN_EPS  1e-5f

// ---------------- device scratch (no allocations allowed) ----------------
__device__ __align__(16) __half g_emb_h[(size_t)VOCAB * HID];  // 51.2 MB fp16 table
__device__ __align__(16) float g_segsum[BATCH * HID];          // 4 MB
__device__ __align__(16) float g_h[BATCH * HID];               // 4 MB
__device__ __align__(16) float g_counts[BATCH];
__device__ __align__(16) float g_sums[HID];
__device__ __align__(16) float g_sumsq[HID];
__device__ float g_loss;
__device__ int   g_nz;     // nonzero odd words => int32 ids
__device__ int   g_done;   // ticket for loss finalization

// ---------------- prep: fp32->fp16 table convert + zero accum + detect ----
__global__ void __launch_bounds__(256)
k_prep(const float* __restrict__ emb, const int* __restrict__ tok) {
    const int bid = blockIdx.x, tid = threadIdx.x;
    size_t idx = ((size_t)bid * 256 + tid) * 8;
    const float4* src = (const float4*)(emb + idx);
    float4 v0 = src[0];
    float4 v1 = src[1];
    uint4 pack;
    __half2 h;
    h = __floats2half2_rn(v0.x, v0.y); pack.x = *(uint32_t*)&h;
    h = __floats2half2_rn(v0.z, v0.w); pack.y = *(uint32_t*)&h;
    h = __floats2half2_rn(v1.x, v1.y); pack.z = *(uint32_t*)&h;
    h = __floats2half2_rn(v1.z, v1.w); pack.w = *(uint32_t*)&h;
    *(uint4*)(g_emb_h + idx) = pack;

    if (bid < 1024) {
        *(float4*)&g_segsum[bid * 1024 + tid * 4] = make_float4(0.f, 0.f, 0.f, 0.f);
    } else if (bid == 1024) {
        float4 z = make_float4(0.f, 0.f, 0.f, 0.f);
        #pragma unroll
        for (int i = 0; i < 4; i++)
            *(float4*)&g_counts[tid * 16 + i * 4] = z;
        g_sums[tid] = 0.f;
        g_sumsq[tid] = 0.f;
        if (tid == 0) g_loss = 0.f;
    } else if (bid == 1025 && tid < 64) {
        if (tok[2 * tid + 1] != 0) atomicOr(&g_nz, 1);
    }
}

// ---------------- gather + segment sum (fp16 table, fp32 accumulate) ------
// Warp owns 64 tokens. Ids/segs preloaded with 4 coalesced lane-strided LDGs
// and broadcast via shuffle (kills 128 uniform LDGs / ~52MB of L2 sectors).
#define TOK_PER_WARP 64
#define GATHER_WARPS 8

__device__ __forceinline__ void flush_run(int seg, const float* a, int runlen, int lane) {
    float* dst = g_segsum + (size_t)seg * HID + lane * 8;
    asm volatile("red.global.add.v4.f32 [%0], {%1,%2,%3,%4};"
                 :: "l"(dst), "f"(a[0]), "f"(a[1]), "f"(a[2]), "f"(a[3]) : "memory");
    asm volatile("red.global.add.v4.f32 [%0], {%1,%2,%3,%4};"
                 :: "l"(dst + 4), "f"(a[4]), "f"(a[5]), "f"(a[6]), "f"(a[7]) : "memory");
    if (lane == 0) atomicAdd(&g_counts[seg], (float)runlen);
}

__global__ void __launch_bounds__(GATHER_WARPS * 32)
k_gather(const int* __restrict__ tok, const int* __restrict__ seg) {
    const int stride = g_nz ? 1 : 2;
    const int lane = threadIdx.x & 31;
    const int warp_id = blockIdx.x * GATHER_WARPS + (threadIdx.x >> 5);
    const int t0 = warp_id * TOK_PER_WARP;

    // preload this warp's 64 token ids + 64 segment ids (coalesced)
    int idp[2], sgp[2];
    idp[0] = tok[(size_t)(t0 + lane) * stride];
    idp[1] = tok[(size_t)(t0 + 32 + lane) * stride];
    sgp[0] = seg[(size_t)(t0 + lane) * stride];
    sgp[1] = seg[(size_t)(t0 + 32 + lane) * stride];

    float a[8];
    #pragma unroll
    for (int i = 0; i < 8; i++) a[i] = 0.f;
    int cur = __shfl_sync(0xFFFFFFFFu, sgp[0], 0);
    int runlen = 0;

    const size_t lane_off = lane * 8;

    #pragma unroll
    for (int hf = 0; hf < 2; ++hf) {
        #pragma unroll 8
        for (int i = 0; i < 32; ++i) {
            int s  = __shfl_sync(0xFFFFFFFFu, sgp[hf], i);
            int id = __shfl_sync(0xFFFFFFFFu, idp[hf], i);
            if (s != cur) {
                flush_run(cur, a, runlen, lane);
                #pragma unroll
                for (int j = 0; j < 8; j++) a[j] = 0.f;
                runlen = 0;
                cur = s;
            }
            uint4 v = *(const uint4*)(g_emb_h + (size_t)id * HID + lane_off);
            const __half2* hp = (const __half2*)&v;
            float2 f;
            f = __half22float2(hp[0]); a[0] += f.x; a[1] += f.y;
            f = __half22float2(hp[1]); a[2] += f.x; a[3] += f.y;
            f = __half22float2(hp[2]); a[4] += f.x; a[5] += f.y;
            f = __half22float2(hp[3]); a[6] += f.x; a[7] += f.y;
            ++runlen;
        }
    }
    flush_run(cur, a, runlen, lane);
}

// ---------------- GEMM: h = (segsum*invc) @ W1^T + b1 (fp16 mma) ----------
// Block tile 128x64, BK=32, 256 threads (8 warps: 4 M x 2 N, warp tile 32x32).
// Single fp16 product (f32 accumulate). BN statistics fused into epilogue.
#define BM 128
#define BN 64
#define BK 32
#define KPAD 40

__device__ __forceinline__ void ldsm4(uint32_t& r0, uint32_t& r1, uint32_t& r2,
                                      uint32_t& r3, const void* p) {
    uint32_t addr = (uint32_t)__cvta_generic_to_shared(p);
    asm volatile("ldmatrix.sync.aligned.m8n8.x4.shared.b16 {%0,%1,%2,%3}, [%4];"
                 : "=r"(r0), "=r"(r1), "=r"(r2), "=r"(r3) : "r"(addr));
}

__device__ __forceinline__ void mma16816h(float* c, uint32_t a0, uint32_t a1,
                                          uint32_t a2, uint32_t a3,
                                          uint32_t b0, uint32_t b1) {
    asm volatile(
        "mma.sync.aligned.m16n8k16.row.col.f32.f16.f16.f32 "
        "{%0,%1,%2,%3}, {%4,%5,%6,%7}, {%8,%9}, {%0,%1,%2,%3};"
        : "+f"(c[0]), "+f"(c[1]), "+f"(c[2]), "+f"(c[3])
        : "r"(a0), "r"(a1), "r"(a2), "r"(a3), "r"(b0), "r"(b1));
}

__global__ void __launch_bounds__(256)
k_gemm(const float* __restrict__ W1, const float* __restrict__ b1) {
    __shared__ __half sA[BM][KPAD];
    __shared__ __half sB[BN][KPAD];
    __shared__ float s_stat[2][BN];

    const int tid = threadIdx.x;
    const int m0 = blockIdx.y * BM;
    const int n0 = blockIdx.x * BN;

    if (tid < BN) { s_stat[0][tid] = 0.f; s_stat[1][tid] = 0.f; }

    const int ar = tid >> 1;
    const int ak = (tid & 1) * 16;
    const int br = tid >> 2;
    const int bk = (tid & 3) * 8;

    const float invc = 1.f / fmaxf(g_counts[m0 + ar], 1.f);

    const int warp = tid >> 5, lane = tid & 31;
    const int wm0 = (warp >> 1) * 32;
    const int wn0 = (warp & 1) * 32;
    const int q = lane >> 3, r = lane & 7;

    float acc[2][4][4];
    #pragma unroll
    for (int i = 0; i < 2; i++)
        #pragma unroll
        for (int j = 0; j < 4; j++)
            #pragma unroll
            for (int k = 0; k < 4; k++) acc[i][j][k] = 0.f;

    float aR[16], bR[8];

    #pragma unroll
    for (int i = 0; i < 4; i++)
        *(float4*)&aR[i * 4] = *(const float4*)&g_segsum[(size_t)(m0 + ar) * HID + ak + i * 4];
    #pragma unroll
    for (int i = 0; i < 2; i++)
        *(float4*)&bR[i * 4] = *(const float4*)&W1[(size_t)(n0 + br) * HID + bk + i * 4];

    for (int k0 = 0; k0 < HID; k0 += BK) {
        #pragma unroll
        for (int i = 0; i < 16; i += 2) {
            __half2 p = __floats2half2_rn(aR[i] * invc, aR[i + 1] * invc);
            *(uint32_t*)&sA[ar][ak + i] = *(uint32_t*)&p;
        }
        #pragma unroll
        for (int i = 0; i < 8; i += 2) {
            __half2 p = __floats2half2_rn(bR[i], bR[i + 1]);
            *(uint32_t*)&sB[br][bk + i] = *(uint32_t*)&p;
        }
        __syncthreads();

        const int kn = k0 + BK;
        if (kn < HID) {
            #pragma unroll
            for (int i = 0; i < 4; i++)
                *(float4*)&aR[i * 4] = *(const float4*)&g_segsum[(size_t)(m0 + ar) * HID + kn + ak + i * 4];
            #pragma unroll
            for (int i = 0; i < 2; i++)
                *(float4*)&bR[i * 4] = *(const float4*)&W1[(size_t)(n0 + br) * HID + kn + bk + i * 4];
        }

        #pragma unroll
        for (int kk = 0; kk < BK; kk += 16) {
            uint32_t ah[2][4], bh[2][4];
            #pragma unroll
            for (int mt = 0; mt < 2; mt++) {
                const int row = wm0 + mt * 16 + (q & 1) * 8 + r;
                const int col = kk + (q >> 1) * 8;
                ldsm4(ah[mt][0], ah[mt][1], ah[mt][2], ah[mt][3], &sA[row][col]);
            }
            #pragma unroll
            for (int p = 0; p < 2; p++) {
                const int row = wn0 + p * 16 + (q >> 1) * 8 + r;
                const int col = kk + (q & 1) * 8;
                ldsm4(bh[p][0], bh[p][1], bh[p][2], bh[p][3], &sB[row][col]);
            }
            #pragma unroll
            for (int mt = 0; mt < 2; mt++)
                #pragma unroll
                for (int nt = 0; nt < 4; nt++)
                    mma16816h(acc[mt][nt], ah[mt][0], ah[mt][1], ah[mt][2], ah[mt][3],
                              bh[nt >> 1][(nt & 1) * 2], bh[nt >> 1][(nt & 1) * 2 + 1]);
        }
        __syncthreads();
    }

    // epilogue: + b1, write g_h, fused BN statistics
    #pragma unroll
    for (int nt = 0; nt < 4; nt++) {
        const int col = n0 + wn0 + nt * 8 + (lane & 3) * 2;
        const float bx = b1[col], by = b1[col + 1];
        float sx = 0.f, sy = 0.f, qx = 0.f, qy = 0.f;
        #pragma unroll
        for (int mt = 0; mt < 2; mt++) {
            const int row = m0 + wm0 + mt * 16 + (lane >> 2);
            float ox0 = acc[mt][nt][0] + bx, oy0 = acc[mt][nt][1] + by;
            float ox1 = acc[mt][nt][2] + bx, oy1 = acc[mt][nt][3] + by;
            *(float2*)&g_h[(size_t)row * HID + col] = make_float2(ox0, oy0);
            *(float2*)&g_h[(size_t)(row + 8) * HID + col] = make_float2(ox1, oy1);
            sx += ox0 + ox1;           sy += oy0 + oy1;
            qx = fmaf(ox0, ox0, qx);   qx = fmaf(ox1, ox1, qx);
            qy = fmaf(oy0, oy0, qy);   qy = fmaf(oy1, oy1, qy);
        }
        #pragma unroll
        for (int off = 16; off >= 4; off >>= 1) {
            sx += __shfl_down_sync(0xFFFFFFFFu, sx, off);
            sy += __shfl_down_sync(0xFFFFFFFFu, sy, off);
            qx += __shfl_down_sync(0xFFFFFFFFu, qx, off);
            qy += __shfl_down_sync(0xFFFFFFFFu, qy, off);
        }
        if (lane < 4) {
            const int c = wn0 + nt * 8 + lane * 2;
            atomicAdd(&s_stat[0][c], sx);
            atomicAdd(&s_stat[0][c + 1], sy);
            atomicAdd(&s_stat[1][c], qx);
            atomicAdd(&s_stat[1][c + 1], qy);
        }
    }
    __syncthreads();
    if (tid < BN) {
        atomicAdd(&g_sums[n0 + tid], s_stat[0][tid]);
        atomicAdd(&g_sumsq[n0 + tid], s_stat[1][tid]);
    }
}

// ---------------- BN + ReLU + W2 dot + BCE + loss finalize ----------------
// 128 blocks x 256 threads; 4 rows per warp (MLP=8), interleaved reduces.
__global__ void __launch_bounds__(256)
k_logits(const float* __restrict__ gamma, const float* __restrict__ beta,
         const float* __restrict__ W2, const float* __restrict__ b2,
         const float* __restrict__ labels, float* __restrict__ out) {
    __shared__ __align__(16) float sc_s[HID];
    __shared__ __align__(16) float sh_s[HID];
    __shared__ __align__(16) float w2_s[HID];
    __shared__ float s_loss;

    const int tid = threadIdx.x;
    if (tid == 0) s_loss = 0.f;
    {
        int j = tid;
        float mean = g_sums[j] * (1.f / BATCH);
        float var = fmaxf(g_sumsq[j] * (1.f / BATCH) - mean * mean, 0.f);
        float rstd = rsqrtf(var + BN_EPS);
        float sc = gamma[j] * rstd;
        sc_s[j] = sc;
        sh_s[j] = fmaf(-mean, sc, beta[j]);
        w2_s[j] = W2[j];
    }
    __syncthreads();

    const int lane = tid & 31;
    const int warp = tid >> 5;
    const int d0 = lane * 8;

    float4 sc0 = *(const float4*)&sc_s[d0];
    float4 sc1 = *(const float4*)&sc_s[d0 + 4];
    float4 sh0 = *(const float4*)&sh_s[d0];
    float4 sh1 = *(const float4*)&sh_s[d0 + 4];
    float4 w0 = *(const float4*)&w2_s[d0];
    float4 w1 = *(const float4*)&w2_s[d0 + 4];
    float bias2 = b2[0];

    const int row0 = blockIdx.x * 32 + warp * 4;

    // load all 4 rows first (8 outstanding LDG.128)
    float4 v0[4], v1[4];
    #pragma unroll
    for (int rr = 0; rr < 4; ++rr) {
        const float4* hp = (const float4*)(g_h + (size_t)(row0 + rr) * HID);
        v0[rr] = hp[lane * 2];
        v1[rr] = hp[lane * 2 + 1];
    }

    float s[4];
    #pragma unroll
    for (int rr = 0; rr < 4; ++rr) {
        float acc = 0.f, x;
        x = fmaxf(fmaf(v0[rr].x, sc0.x, sh0.x), 0.f); acc = fmaf(x, w0.x, acc);
        x = fmaxf(fmaf(v0[rr].y, sc0.y, sh0.y), 0.f); acc = fmaf(x, w0.y, acc);
        x = fmaxf(fmaf(v0[rr].z, sc0.z, sh0.z), 0.f); acc = fmaf(x, w0.z, acc);
        x = fmaxf(fmaf(v0[rr].w, sc0.w, sh0.w), 0.f); acc = fmaf(x, w0.w, acc);
        x = fmaxf(fmaf(v1[rr].x, sc1.x, sh1.x), 0.f); acc = fmaf(x, w1.x, acc);
        x = fmaxf(fmaf(v1[rr].y, sc1.y, sh1.y), 0.f); acc = fmaf(x, w1.y, acc);
        x = fmaxf(fmaf(v1[rr].z, sc1.z, sh1.z), 0.f); acc = fmaf(x, w1.z, acc);
        x = fmaxf(fmaf(v1[rr].w, sc1.w, sh1.w), 0.f); acc = fmaf(x, w1.w, acc);
        s[rr] = acc;
    }

    // interleaved reduction: 4 independent chains hide shuffle latency
    #pragma unroll
    for (int off = 16; off > 0; off >>= 1) {
        #pragma unroll
        for (int rr = 0; rr < 4; ++rr)
            s[rr] += __shfl_down_sync(0xFFFFFFFFu, s[rr], off);
    }

    if (lane == 0) {
        float lacc = 0.f;
        #pragma unroll
        for (int rr = 0; rr < 4; ++rr) {
            float logit = s[rr] + bias2;
            out[1 + row0 + rr] = logit;
            float y = labels[row0 + rr];
            lacc += fmaxf(logit, 0.f) - logit * y + log1pf(expf(-fabsf(logit)));
        }
        atomicAdd(&s_loss, lacc);
    }
    __syncthreads();
    if (tid == 0) {
        atomicAdd(&g_loss, s_loss);
        __threadfence();
        int old = atomicAdd(&g_done, 1);
        if (old == (int)gridDim.x - 1) {
            g_done = 0;
            float L = atomicAdd(&g_loss, 0.f);
            out[0] = L * (1.f / BATCH);
        }
    }
}

// ---------------- launch ----------------
extern "C" void kernel_launch(void* const* d_in, const int* in_sizes, int n_in,
                              void* d_out, int out_size) {
    const int*   tok    = (const int*)d_in[0];
    const int*   seg    = (const int*)d_in[1];
    const float* labels = (const float*)d_in[2];
    const float* emb    = (const float*)d_in[3];
    const float* W1     = (const float*)d_in[4];
    const float* b1     = (const float*)d_in[5];
    const float* gamma  = (const float*)d_in[6];
    const float* beta   = (const float*)d_in[7];
    const float* W2     = (const float*)d_in[8];
    const float* b2     = (const float*)d_in[9];
    float* out = (float*)d_out;

    k_prep<<<(VOCAB * HID) / (256 * 8), 256>>>(emb, tok);
    k_gather<<<N_TOK / (TOK_PER_WARP * GATHER_WARPS), GATHER_WARPS * 32>>>(tok, seg);
    k_gemm<<<dim3(HID / BN, BATCH / BM), 256>>>(W1, b1);
    k_logits<<<BATCH / 32, 256>>>(gamma, beta, W2, b2, labels, out);
}